// round 15
// baseline (speedup 1.0000x reference)
#include <cuda_runtime.h>
#include <cuda_fp16.h>
#include <math.h>
#include <stdint.h>

// Problem shape (fixed by reference): B=4, S=2048, D=1024
#define BATCH 4
#define SEQ   2048
#define DIM   1024
#define NTOK  (BATCH * SEQ)   // 8192

// ---------------------------------------------------------------------------
// Scratch (static device globals)
// ---------------------------------------------------------------------------
__device__ __half g_xh[NTOK * DIM];
__device__ __half g_Wqkh[2048 * DIM];                        // [Qw^T; Kw^T] hi
__device__ __half g_Wvh[DIM * DIM];                          // Vw^T hi
__device__ __half g_QKh[NTOK * 2048];                        // Q(pre-scaled) | K
__device__ __half g_Vth[DIM * NTOK];                         // V^T [D, NTOK]
__device__ __half g_Eh[BATCH * SEQ * SEQ];                   // exp(logits), masked
__device__ float  g_rowsum[BATCH * SEQ];                     // softmax denominators
// counters: [0,3) w-matrix (64 each), [4,36) x band (1 each),
//           [36,68) qk row-band (16 each), [68,84) v D-band x batch (16 each),
//           [84,116) scores band (2i+2 each)
__device__ int    g_ready[116];

// ---------------------------------------------------------------------------
// Helpers
// ---------------------------------------------------------------------------
__device__ __forceinline__ uint32_t smem_u32(const void* p) {
    uint32_t a;
    asm("{ .reg .u64 t; cvta.to.shared.u64 t, %1; cvt.u32.u64 %0, t; }" : "=r"(a) : "l"(p));
    return a;
}

__device__ __forceinline__ void spin_until(const int* cp, int need) {
    int v;
    do {
        asm volatile("ld.acquire.gpu.u32 %0, [%1];" : "=r"(v) : "l"(cp) : "memory");
        if (v < need) __nanosleep(200);
    } while (v < need);
}

#define CP16(dst, src) \
    asm volatile("cp.async.cg.shared.global [%0], [%1], 16;" :: "r"(dst), "l"(src))

#define LDSM4(r, addr) \
    asm volatile("ldmatrix.sync.aligned.m8n8.x4.shared.b16 {%0,%1,%2,%3}, [%4];" \
        : "=r"((r)[0]), "=r"((r)[1]), "=r"((r)[2]), "=r"((r)[3]) : "r"(addr))

// fp32-accumulate MMA
#define MMA4(c, a, b0, b1) \
    asm volatile("mma.sync.aligned.m16n8k16.row.col.f32.f16.f16.f32 " \
        "{%0,%1,%2,%3}, {%4,%5,%6,%7}, {%8,%9}, {%0,%1,%2,%3};" \
        : "+f"((c)[0]), "+f"((c)[1]), "+f"((c)[2]), "+f"((c)[3]) \
        : "r"((a)[0]), "r"((a)[1]), "r"((a)[2]), "r"((a)[3]), "r"(b0), "r"(b1))

// ---------------------------------------------------------------------------
// Unified GEMM body: CTA tile 256x128, BK=64, 512 threads = 16 warps (4x4),
// warp tile 64x32, 3-stage cp.async pipeline, 144B pitch (conflict-free LDSM).
// EPI: 2 -> fp16 Ch, scaled by cmul
//      3 -> fp16 exp(acc) with causal mask; row sums -> rsum_sh -> rs_out
//      4 -> fp32 C divided by rs_in[row]
// ---------------------------------------------------------------------------
#define PITCH    144
#define TILE_A64 (256 * PITCH)     // 36864
#define TILE_B64 (128 * PITCH)     // 18432
#define STAGE_G  (TILE_A64 + TILE_B64)
#define SMEM_G   (3 * STAGE_G)     // 165888

template <int EPI>
__device__ __forceinline__ void gemm_body(
    const __half* __restrict__ Ah, const __half* __restrict__ Bh,
    float* __restrict__ C, __half* __restrict__ Ch,
    int lda, int ldb, int ldc, int brow0, int bcol0, int kend, float cmul,
    char* sm, float* rsum_sh, float* rs_out, const float* rs_in)
{
    const uint32_t smb = smem_u32(sm);

    const int tid = threadIdx.x;
    const int lane = tid & 31;
    const int wid = tid >> 5;     // 0..15
    const int wr = wid >> 2;      // 0..3 -> rows wr*64
    const int wc = wid & 3;       // 0..3 -> cols wc*32

    const int nsteps = kend >> 6;          // BK = 64

    const int lrow = tid >> 3;    // 0..63
    const int lcol = tid & 7;     // 0..7 (16B chunks over 128B row)
    const uint32_t soR = (uint32_t)(lrow * PITCH + lcol * 16);

    auto load_stage = [&](int slot, int k0) {
        uint32_t st = smb + slot * STAGE_G;
        long gk = k0 + lcol * 8;
#pragma unroll
        for (int h = 0; h < 4; h++)
            CP16(st + soR + h * (64 * PITCH),
                 Ah + (long)(brow0 + lrow + h * 64) * lda + gk);
#pragma unroll
        for (int h = 0; h < 2; h++)
            CP16(st + TILE_A64 + soR + h * (64 * PITCH),
                 Bh + (long)(bcol0 + lrow + h * 64) * ldb + gk);
        asm volatile("cp.async.commit_group;");
    };

    float acc[4][4][4];
#pragma unroll
    for (int mt = 0; mt < 4; mt++)
#pragma unroll
        for (int nt = 0; nt < 4; nt++)
#pragma unroll
            for (int v = 0; v < 4; v++) acc[mt][nt][v] = 0.f;

    const int arow = lane & 15;
    const int asel = lane >> 4;
    const int browi = (lane & 7) + ((lane >> 4) << 3);
    const int bsel = (lane >> 3) & 1;

#pragma unroll
    for (int k = 0; k < 2; k++) {
        if (k < nsteps) load_stage(k, k * 64);
        else asm volatile("cp.async.commit_group;");
    }

    for (int s = 0; s < nsteps; s++) {
        asm volatile("cp.async.wait_group 1;");
        __syncthreads();

        const uint32_t st = smb + (s % 3) * STAGE_G;
#pragma unroll
        for (int kk = 0; kk < 4; kk++) {
            uint32_t aH[4][4];
#pragma unroll
            for (int mt = 0; mt < 4; mt++) {
                uint32_t off = (uint32_t)((wr * 64 + mt * 16 + arow) * PITCH + kk * 32 + asel * 16);
                LDSM4(aH[mt], st + off);
            }
            uint32_t bH[2][4];
#pragma unroll
            for (int np = 0; np < 2; np++) {
                uint32_t off = (uint32_t)((wc * 32 + np * 16 + browi) * PITCH + kk * 32 + bsel * 16);
                LDSM4(bH[np], st + TILE_A64 + off);
            }
#pragma unroll
            for (int mt = 0; mt < 4; mt++)
#pragma unroll
                for (int nt = 0; nt < 4; nt++) {
                    const int np = nt >> 1, hv = (nt & 1) * 2;
                    MMA4(acc[mt][nt], aH[mt], bH[np][hv], bH[np][hv + 1]);
                }
        }

        if (s + 2 < nsteps) load_stage((s + 2) % 3, (s + 2) * 64);
        else asm volatile("cp.async.commit_group;");
    }

    // --- epilogue ---
    if (EPI == 3) {
        __syncthreads();
        if (tid < 256) rsum_sh[tid] = 0.f;
        __syncthreads();
    }

    const int erow = lane >> 2;
    const int ecol = (lane & 3) * 2;
#pragma unroll
    for (int mt = 0; mt < 4; mt++) {
        const int row = brow0 + wr * 64 + mt * 16 + erow;
        float rp0 = 0.f, rp1 = 0.f;         // EPI==3 row partials
        float i0 = 1.f, i1 = 1.f;
        if (EPI == 4) {
            i0 = __frcp_rn(rs_in[row]);
            i1 = __frcp_rn(rs_in[row + 8]);
        }
#pragma unroll
        for (int nt = 0; nt < 4; nt++) {
            const int col = bcol0 + wc * 32 + nt * 8 + ecol;
            float c0 = acc[mt][nt][0], c1 = acc[mt][nt][1];
            float c2 = acc[mt][nt][2], c3 = acc[mt][nt][3];
            if (EPI == 4) {
                c0 *= i0; c1 *= i0; c2 *= i1; c3 *= i1;
                *(float2*)(C + (long)row * ldc + col)       = make_float2(c0, c1);
                *(float2*)(C + (long)(row + 8) * ldc + col) = make_float2(c2, c3);
            } else if (EPI == 2) {
                c0 *= cmul; c1 *= cmul; c2 *= cmul; c3 *= cmul;
                *(__half2*)(Ch + (long)row * ldc + col) =
                    __halves2half2(__float2half_rn(c0), __float2half_rn(c1));
                *(__half2*)(Ch + (long)(row + 8) * ldc + col) =
                    __halves2half2(__float2half_rn(c2), __float2half_rn(c3));
            } else { // EPI == 3: exp + causal mask + row sums
                float e0 = (col     <= row)     ? __expf(c0) : 0.f;
                float e1 = (col + 1 <= row)     ? __expf(c1) : 0.f;
                float e2 = (col     <= row + 8) ? __expf(c2) : 0.f;
                float e3 = (col + 1 <= row + 8) ? __expf(c3) : 0.f;
                *(__half2*)(Ch + (long)row * ldc + col) =
                    __halves2half2(__float2half_rn(e0), __float2half_rn(e1));
                *(__half2*)(Ch + (long)(row + 8) * ldc + col) =
                    __halves2half2(__float2half_rn(e2), __float2half_rn(e3));
                rp0 += e0 + e1;
                rp1 += e2 + e3;
            }
        }
        if (EPI == 3) {
            rp0 += __shfl_xor_sync(0xFFFFFFFFu, rp0, 1);
            rp0 += __shfl_xor_sync(0xFFFFFFFFu, rp0, 2);
            rp1 += __shfl_xor_sync(0xFFFFFFFFu, rp1, 1);
            rp1 += __shfl_xor_sync(0xFFFFFFFFu, rp1, 2);
            if ((lane & 3) == 0) {
                const int rl = wr * 64 + mt * 16 + erow;
                atomicAdd(&rsum_sh[rl],     rp0);
                atomicAdd(&rsum_sh[rl + 8], rp1);
            }
        }
    }
    if (EPI == 3) {
        __syncthreads();
        if (tid < 256) atomicAdd(&rs_out[brow0 + tid], rsum_sh[tid]);
    }
}

// ---------------------------------------------------------------------------
// Mega kernel: one grid, counter-pipelined stages.
//   ids [0,192):     weight transpose (128x128 tiles; Qw,Kw,Vw).
//   ids [192,224):   x fp32->fp16 convert (one 256-row band each, ascending).
//   ids [224,736):   QK projection, gated on ready_w + ready_x.
//   ids [736,992):   V^T projection, gated on ready_w + ready_x.
//   ids [992,1280):  scores+exp+rowsum, gated on ready_qk; heavy bands first.
//   ids [1280,1536): PV, gated on scores band + ready_v counters.
// All consumer ids exceed producer ids -> in-order dispatch keeps spins short.
// Counters/rowsum are zeroed by cudaMemsetAsync before this launch.
// ---------------------------------------------------------------------------
__global__ void __launch_bounds__(512, 1)
mega_k(const float* __restrict__ x, const float* __restrict__ Qw,
       const float* __restrict__ Kw, const float* __restrict__ Vw,
       __half* __restrict__ xh, __half* __restrict__ Wqkh,
       __half* __restrict__ Wvh, __half* __restrict__ QKh,
       __half* __restrict__ Vth, __half* __restrict__ Eh,
       float* __restrict__ rowsum, float* __restrict__ out,
       int* __restrict__ ready)
{
    extern __shared__ char sm[];
    __shared__ float rsum_sh[256];
    const int bid = blockIdx.x;
    const int tid = threadIdx.x;

    int* ready_w    = ready;         // [0,3)   need 64
    int* ready_x    = ready + 4;     // [4,36)  need 1
    int* ready_qk   = ready + 36;    // [36,68) need 16
    int* ready_v    = ready + 68;    // [68,84) need 16
    int* ready_band = ready + 84;    // [84,116) need 2i+2

    if (bid < 192) {
        // ---- weight transpose: 128x128 tile, 512 threads ----
        const int m = bid >> 6;             // 0=Qw, 1=Kw, 2=Vw
        const int t = bid & 63;
        const int r0 = (t >> 3) * 128;      // source row block
        const int c0 = (t & 7) * 128;       // source col block
        const float* src = (m == 0) ? Qw : (m == 1) ? Kw : Vw;
        __half* dst = (m == 0) ? Wqkh : (m == 1) ? (Wqkh + DIM * DIM) : Wvh;

        float* tile = (float*)sm;           // [128][132]
        const int tx = tid & 127;
        const int ty0 = tid >> 7;           // 0..3
#pragma unroll 4
        for (int dy = ty0; dy < 128; dy += 4)
            tile[dy * 132 + tx] = src[(long)(r0 + dy) * DIM + c0 + tx];
        __syncthreads();
#pragma unroll 4
        for (int dy = ty0; dy < 128; dy += 4)
            dst[(long)(c0 + dy) * DIM + r0 + tx] =
                __float2half_rn(tile[tx * 132 + dy]);
        __syncthreads();
        if (tid == 0) {
            __threadfence();
            atomicAdd(&ready_w[m], 1);
        }
    } else if (bid < 224) {
        // ---- x convert: one 256-row band ----
        const int b = bid - 192;
        const long base = (long)b * 256 * DIM / 4;    // in float4 units
        const long cnt = 256L * DIM / 4;              // 65536
        for (long i = tid; i < cnt; i += 512) {
            float4 v = ((const float4*)x)[base + i];
            __half h[4] = {__float2half_rn(v.x), __float2half_rn(v.y),
                           __float2half_rn(v.z), __float2half_rn(v.w)};
            ((uint2*)xh)[base + i] = *(uint2*)h;
        }
        __threadfence();
        __syncthreads();
        if (tid == 0) atomicAdd(&ready_x[b], 1);
    } else if (bid < 736) {
        // ---- QK projection: bx 0..15 (cols), by 0..31 (row band, batch-major)
        const int id2 = bid - 224;
        const int bx = id2 & 15, by = id2 >> 4;
        const float cmul = (bx < 8) ? 0.03125f : 1.0f;   // scale Q columns only
        if (tid == 0) {
            spin_until(&ready_w[bx < 8 ? 0 : 1], 64);
            spin_until(&ready_x[by], 1);
        }
        __syncthreads();
        gemm_body<2>(xh, Wqkh, nullptr, QKh, DIM, DIM, 2048,
                     by * 256, bx * 128, DIM, cmul, sm, nullptr, nullptr, nullptr);
        __syncthreads();
        if (tid == 0) {
            __threadfence();
            atomicAdd(&ready_qk[by], 1);
        }
    } else if (bid < 992) {
        // ---- V^T projection: bx 0..63 (token blocks), by 0..3 (D band)
        const int id2 = bid - 736;
        const int bx = id2 & 63, by = id2 >> 6;
        if (tid == 0) {
            spin_until(&ready_w[2], 64);
            spin_until(&ready_x[bx >> 1], 1);
        }
        __syncthreads();
        gemm_body<2>(Wvh, xh, nullptr, Vth, DIM, DIM, NTOK,
                     by * 256, bx * 128, DIM, 1.0f, sm, nullptr, nullptr, nullptr);
        __syncthreads();
        if (tid == 0) {
            __threadfence();
            atomicAdd(&ready_v[by * 4 + (bx >> 4)], 1);
        }
    } else if (bid < 1280) {
        // ---- scores block ----
        const int sid = bid - 992;
        const int z = sid & 3;
        const int t = 71 - (sid >> 2);      // heavy bands first
        int i = 0;
        while ((i + 1) * (i + 2) <= t) ++i;
        const int j = t - i * (i + 1);

        if (tid == 0) {
            spin_until(&ready_qk[z * 8 + i], 16);          // Q band
            spin_until(&ready_qk[z * 8 + (j >> 1)], 16);   // K band
        }
        __syncthreads();

        const __half* A = QKh + (long)z * SEQ * 2048;
        const __half* B = QKh + 1024 + (long)z * SEQ * 2048;
        __half* Cc = Eh + (long)z * SEQ * SEQ;
        gemm_body<3>(A, B, nullptr, Cc, 2048, 2048, SEQ,
                     i * 256, j * 128, DIM, 1.0f, sm, rsum_sh,
                     rowsum + (long)z * SEQ, nullptr);

        __syncthreads();
        if (tid == 0) {
            __threadfence();
            atomicAdd(&ready_band[z * 8 + i], 1);
        }
    } else {
        // ---- PV block ----
        const int p = bid - 1280;
        const int z = p & 3;
        const int pp = p >> 2;              // 0..63
        const int by = 7 - (pp >> 3);       // heavy bands first
        const int bx = pp & 7;
        const int brow0 = by * 256;

        if (tid == 0) {
            spin_until(&ready_band[z * 8 + by], 2 * by + 2);   // scores band
            spin_until(&ready_v[(bx >> 1) * 4 + z], 16);       // V proj band
        }
        __syncthreads();

        const __half* A = Eh + (long)z * SEQ * SEQ;
        const __half* B = Vth + (long)z * SEQ;
        float* Cc = out + (long)z * SEQ * DIM;
        gemm_body<4>(A, B, Cc, nullptr, SEQ, NTOK, DIM,
                     brow0, bx * 128, brow0 + 256, 1.0f, sm,
                     nullptr, nullptr, rowsum + (long)z * SEQ);
    }
}

// ---------------------------------------------------------------------------
// Host launcher
// ---------------------------------------------------------------------------
extern "C" void kernel_launch(void* const* d_in, const int* in_sizes, int n_in,
                              void* d_out, int out_size)
{
    (void)in_sizes; (void)n_in; (void)out_size;
    const float* x  = (const float*)d_in[0];
    const float* Qw = (const float*)d_in[1];
    const float* Kw = (const float*)d_in[2];
    const float* Vw = (const float*)d_in[3];
    float* out = (float*)d_out;

    __half *xh, *Wqkh, *Wvh, *QKh, *Vth, *Eh;
    float* rowsum;
    int* ready;
    cudaGetSymbolAddress((void**)&xh,     g_xh);
    cudaGetSymbolAddress((void**)&Wqkh,   g_Wqkh);
    cudaGetSymbolAddress((void**)&Wvh,    g_Wvh);
    cudaGetSymbolAddress((void**)&QKh,    g_QKh);
    cudaGetSymbolAddress((void**)&Vth,    g_Vth);
    cudaGetSymbolAddress((void**)&Eh,     g_Eh);
    cudaGetSymbolAddress((void**)&rowsum, g_rowsum);
    cudaGetSymbolAddress((void**)&ready,  g_ready);

    cudaFuncSetAttribute(mega_k, cudaFuncAttributeMaxDynamicSharedMemorySize, SMEM_G);

    // Reset pipeline state (graph-capturable async memsets).
    cudaMemsetAsync(ready, 0, 116 * sizeof(int));
    cudaMemsetAsync(rowsum, 0, BATCH * SEQ * sizeof(float));

    // Entire computation: one counter-pipelined grid.
    mega_k<<<1536, 512, SMEM_G>>>(x, Qw, Kw, Vw, xh, Wqkh, Wvh,
                                  QKh, Vth, Eh, rowsum, out, ready);
}

// round 16
// speedup vs baseline: 1.0229x; 1.0229x over previous
#include <cuda_runtime.h>
#include <cuda_fp16.h>
#include <math.h>
#include <stdint.h>

// Problem shape (fixed by reference): B=4, S=2048, D=1024
#define BATCH 4
#define SEQ   2048
#define DIM   1024
#define NTOK  (BATCH * SEQ)   // 8192

// ---------------------------------------------------------------------------
// Scratch (static device globals)
// ---------------------------------------------------------------------------
__device__ __half g_xh[NTOK * DIM];
__device__ __half g_Wqkh[2048 * DIM];                        // [Qw^T; Kw^T] hi
__device__ __half g_Wvh[DIM * DIM];                          // Vw^T hi
__device__ __half g_QKh[NTOK * 2048];                        // Q(pre-scaled) | K
__device__ __half g_Vth[DIM * NTOK];                         // V^T [D, NTOK]
__device__ __half g_Eh[BATCH * SEQ * SEQ];                   // exp(logits), masked
__device__ float  g_rowsum[BATCH * SEQ];                     // softmax denominators
// counters: [0,3) w-matrix (64 each), [4,36) x band (8 each),
//           [36,68) qk row-band (16 each), [68,84) v D-band x batch (16 each),
//           [84,116) scores band (2i+2 each)
__device__ int    g_ready[116];

// ---------------------------------------------------------------------------
// Helpers
// ---------------------------------------------------------------------------
__device__ __forceinline__ uint32_t smem_u32(const void* p) {
    uint32_t a;
    asm("{ .reg .u64 t; cvta.to.shared.u64 t, %1; cvt.u32.u64 %0, t; }" : "=r"(a) : "l"(p));
    return a;
}

__device__ __forceinline__ void spin_until(const int* cp, int need) {
    int v;
    do {
        asm volatile("ld.acquire.gpu.u32 %0, [%1];" : "=r"(v) : "l"(cp) : "memory");
        if (v < need) __nanosleep(200);
    } while (v < need);
}

#define CP16(dst, src) \
    asm volatile("cp.async.cg.shared.global [%0], [%1], 16;" :: "r"(dst), "l"(src))

#define LDSM4(r, addr) \
    asm volatile("ldmatrix.sync.aligned.m8n8.x4.shared.b16 {%0,%1,%2,%3}, [%4];" \
        : "=r"((r)[0]), "=r"((r)[1]), "=r"((r)[2]), "=r"((r)[3]) : "r"(addr))

// fp32-accumulate MMA
#define MMA4(c, a, b0, b1) \
    asm volatile("mma.sync.aligned.m16n8k16.row.col.f32.f16.f16.f32 " \
        "{%0,%1,%2,%3}, {%4,%5,%6,%7}, {%8,%9}, {%0,%1,%2,%3};" \
        : "+f"((c)[0]), "+f"((c)[1]), "+f"((c)[2]), "+f"((c)[3]) \
        : "r"((a)[0]), "r"((a)[1]), "r"((a)[2]), "r"((a)[3]), "r"(b0), "r"(b1))

// ---------------------------------------------------------------------------
// Unified GEMM body: CTA tile 256x128, BK=64, 512 threads = 16 warps (4x4),
// warp tile 64x32, 3-stage cp.async pipeline, 144B pitch (conflict-free LDSM).
// EPI: 2 -> fp16 Ch, scaled by cmul
//      3 -> fp16 exp(acc) with causal mask; row sums -> rsum_sh -> rs_out
//      4 -> fp32 C divided by rs_in[row]
// ---------------------------------------------------------------------------
#define PITCH    144
#define TILE_A64 (256 * PITCH)     // 36864
#define TILE_B64 (128 * PITCH)     // 18432
#define STAGE_G  (TILE_A64 + TILE_B64)
#define SMEM_G   (3 * STAGE_G)     // 165888

template <int EPI>
__device__ __forceinline__ void gemm_body(
    const __half* __restrict__ Ah, const __half* __restrict__ Bh,
    float* __restrict__ C, __half* __restrict__ Ch,
    int lda, int ldb, int ldc, int brow0, int bcol0, int kend, float cmul,
    char* sm, float* rsum_sh, float* rs_out, const float* rs_in)
{
    const uint32_t smb = smem_u32(sm);

    const int tid = threadIdx.x;
    const int lane = tid & 31;
    const int wid = tid >> 5;     // 0..15
    const int wr = wid >> 2;      // 0..3 -> rows wr*64
    const int wc = wid & 3;       // 0..3 -> cols wc*32

    const int nsteps = kend >> 6;          // BK = 64

    const int lrow = tid >> 3;    // 0..63
    const int lcol = tid & 7;     // 0..7 (16B chunks over 128B row)
    const uint32_t soR = (uint32_t)(lrow * PITCH + lcol * 16);

    auto load_stage = [&](int slot, int k0) {
        uint32_t st = smb + slot * STAGE_G;
        long gk = k0 + lcol * 8;
#pragma unroll
        for (int h = 0; h < 4; h++)
            CP16(st + soR + h * (64 * PITCH),
                 Ah + (long)(brow0 + lrow + h * 64) * lda + gk);
#pragma unroll
        for (int h = 0; h < 2; h++)
            CP16(st + TILE_A64 + soR + h * (64 * PITCH),
                 Bh + (long)(bcol0 + lrow + h * 64) * ldb + gk);
        asm volatile("cp.async.commit_group;");
    };

    float acc[4][4][4];
#pragma unroll
    for (int mt = 0; mt < 4; mt++)
#pragma unroll
        for (int nt = 0; nt < 4; nt++)
#pragma unroll
            for (int v = 0; v < 4; v++) acc[mt][nt][v] = 0.f;

    const int arow = lane & 15;
    const int asel = lane >> 4;
    const int browi = (lane & 7) + ((lane >> 4) << 3);
    const int bsel = (lane >> 3) & 1;

#pragma unroll
    for (int k = 0; k < 2; k++) {
        if (k < nsteps) load_stage(k, k * 64);
        else asm volatile("cp.async.commit_group;");
    }

    for (int s = 0; s < nsteps; s++) {
        asm volatile("cp.async.wait_group 1;");
        __syncthreads();

        const uint32_t st = smb + (s % 3) * STAGE_G;
#pragma unroll
        for (int kk = 0; kk < 4; kk++) {
            uint32_t aH[4][4];
#pragma unroll
            for (int mt = 0; mt < 4; mt++) {
                uint32_t off = (uint32_t)((wr * 64 + mt * 16 + arow) * PITCH + kk * 32 + asel * 16);
                LDSM4(aH[mt], st + off);
            }
            uint32_t bH[2][4];
#pragma unroll
            for (int np = 0; np < 2; np++) {
                uint32_t off = (uint32_t)((wc * 32 + np * 16 + browi) * PITCH + kk * 32 + bsel * 16);
                LDSM4(bH[np], st + TILE_A64 + off);
            }
#pragma unroll
            for (int mt = 0; mt < 4; mt++)
#pragma unroll
                for (int nt = 0; nt < 4; nt++) {
                    const int np = nt >> 1, hv = (nt & 1) * 2;
                    MMA4(acc[mt][nt], aH[mt], bH[np][hv], bH[np][hv + 1]);
                }
        }

        if (s + 2 < nsteps) load_stage((s + 2) % 3, (s + 2) * 64);
        else asm volatile("cp.async.commit_group;");
    }

    // --- epilogue ---
    if (EPI == 3) {
        __syncthreads();
        if (tid < 256) rsum_sh[tid] = 0.f;
        __syncthreads();
    }

    const int erow = lane >> 2;
    const int ecol = (lane & 3) * 2;
#pragma unroll
    for (int mt = 0; mt < 4; mt++) {
        const int row = brow0 + wr * 64 + mt * 16 + erow;
        float rp0 = 0.f, rp1 = 0.f;         // EPI==3 row partials
        float i0 = 1.f, i1 = 1.f;
        if (EPI == 4) {
            i0 = __frcp_rn(rs_in[row]);
            i1 = __frcp_rn(rs_in[row + 8]);
        }
#pragma unroll
        for (int nt = 0; nt < 4; nt++) {
            const int col = bcol0 + wc * 32 + nt * 8 + ecol;
            float c0 = acc[mt][nt][0], c1 = acc[mt][nt][1];
            float c2 = acc[mt][nt][2], c3 = acc[mt][nt][3];
            if (EPI == 4) {
                c0 *= i0; c1 *= i0; c2 *= i1; c3 *= i1;
                *(float2*)(C + (long)row * ldc + col)       = make_float2(c0, c1);
                *(float2*)(C + (long)(row + 8) * ldc + col) = make_float2(c2, c3);
            } else if (EPI == 2) {
                c0 *= cmul; c1 *= cmul; c2 *= cmul; c3 *= cmul;
                *(__half2*)(Ch + (long)row * ldc + col) =
                    __halves2half2(__float2half_rn(c0), __float2half_rn(c1));
                *(__half2*)(Ch + (long)(row + 8) * ldc + col) =
                    __halves2half2(__float2half_rn(c2), __float2half_rn(c3));
            } else { // EPI == 3: exp + causal mask + row sums
                float e0 = (col     <= row)     ? __expf(c0) : 0.f;
                float e1 = (col + 1 <= row)     ? __expf(c1) : 0.f;
                float e2 = (col     <= row + 8) ? __expf(c2) : 0.f;
                float e3 = (col + 1 <= row + 8) ? __expf(c3) : 0.f;
                *(__half2*)(Ch + (long)row * ldc + col) =
                    __halves2half2(__float2half_rn(e0), __float2half_rn(e1));
                *(__half2*)(Ch + (long)(row + 8) * ldc + col) =
                    __halves2half2(__float2half_rn(e2), __float2half_rn(e3));
                rp0 += e0 + e1;
                rp1 += e2 + e3;
            }
        }
        if (EPI == 3) {
            rp0 += __shfl_xor_sync(0xFFFFFFFFu, rp0, 1);
            rp0 += __shfl_xor_sync(0xFFFFFFFFu, rp0, 2);
            rp1 += __shfl_xor_sync(0xFFFFFFFFu, rp1, 1);
            rp1 += __shfl_xor_sync(0xFFFFFFFFu, rp1, 2);
            if ((lane & 3) == 0) {
                const int rl = wr * 64 + mt * 16 + erow;
                atomicAdd(&rsum_sh[rl],     rp0);
                atomicAdd(&rsum_sh[rl + 8], rp1);
            }
        }
    }
    if (EPI == 3) {
        __syncthreads();
        if (tid < 256) atomicAdd(&rs_out[brow0 + tid], rsum_sh[tid]);
    }
}

// ---------------------------------------------------------------------------
// Mega kernel: one grid, counter-pipelined stages.
//   ids [0,192):     weight transpose (128x128 tiles; Qw,Kw,Vw).
//   ids [192,448):   x fp32->fp16 convert (32 rows each; 8 blocks per band).
//   ids [448,960):   QK projection, gated on ready_w + ready_x.
//   ids [960,1216):  V^T projection, gated on ready_w + ready_x.
//   ids [1216,1504): scores+exp+rowsum, gated on ready_qk; heavy bands first.
//   ids [1504,1760): PV, gated on scores band + ready_v counters.
// All consumer ids exceed producer ids -> in-order dispatch keeps spins short.
// Counters/rowsum are zeroed by cudaMemsetAsync before this launch.
// ---------------------------------------------------------------------------
__global__ void __launch_bounds__(512, 1)
mega_k(const float* __restrict__ x, const float* __restrict__ Qw,
       const float* __restrict__ Kw, const float* __restrict__ Vw,
       __half* __restrict__ xh, __half* __restrict__ Wqkh,
       __half* __restrict__ Wvh, __half* __restrict__ QKh,
       __half* __restrict__ Vth, __half* __restrict__ Eh,
       float* __restrict__ rowsum, float* __restrict__ out,
       int* __restrict__ ready)
{
    extern __shared__ char sm[];
    __shared__ float rsum_sh[256];
    const int bid = blockIdx.x;
    const int tid = threadIdx.x;

    int* ready_w    = ready;         // [0,3)   need 64
    int* ready_x    = ready + 4;     // [4,36)  need 8
    int* ready_qk   = ready + 36;    // [36,68) need 16
    int* ready_v    = ready + 68;    // [68,84) need 16
    int* ready_band = ready + 84;    // [84,116) need 2i+2

    if (bid < 192) {
        // ---- weight transpose: 128x128 tile, 512 threads ----
        const int m = bid >> 6;             // 0=Qw, 1=Kw, 2=Vw
        const int t = bid & 63;
        const int r0 = (t >> 3) * 128;      // source row block
        const int c0 = (t & 7) * 128;       // source col block
        const float* src = (m == 0) ? Qw : (m == 1) ? Kw : Vw;
        __half* dst = (m == 0) ? Wqkh : (m == 1) ? (Wqkh + DIM * DIM) : Wvh;

        float* tile = (float*)sm;           // [128][132]
        const int tx = tid & 127;
        const int ty0 = tid >> 7;           // 0..3
#pragma unroll 4
        for (int dy = ty0; dy < 128; dy += 4)
            tile[dy * 132 + tx] = src[(long)(r0 + dy) * DIM + c0 + tx];
        __syncthreads();
#pragma unroll 4
        for (int dy = ty0; dy < 128; dy += 4)
            dst[(long)(c0 + dy) * DIM + r0 + tx] =
                __float2half_rn(tile[tx * 132 + dy]);
        __syncthreads();
        if (tid == 0) {
            __threadfence();
            atomicAdd(&ready_w[m], 1);
        }
    } else if (bid < 448) {
        // ---- x convert: one 32-row slice (8 slices per 256-row band) ----
        const int b = bid - 192;            // 0..255
        const long base = (long)b * 32 * DIM / 4;     // in float4 units
        const long cnt = 32L * DIM / 4;               // 8192
        for (long i = tid; i < cnt; i += 512) {
            float4 v = ((const float4*)x)[base + i];
            __half h[4] = {__float2half_rn(v.x), __float2half_rn(v.y),
                           __float2half_rn(v.z), __float2half_rn(v.w)};
            ((uint2*)xh)[base + i] = *(uint2*)h;
        }
        __threadfence();
        __syncthreads();
        if (tid == 0) atomicAdd(&ready_x[b >> 3], 1);
    } else if (bid < 960) {
        // ---- QK projection: bx 0..15 (cols), by 0..31 (row band, batch-major)
        const int id2 = bid - 448;
        const int bx = id2 & 15, by = id2 >> 4;
        const float cmul = (bx < 8) ? 0.03125f : 1.0f;   // scale Q columns only
        if (tid == 0) {
            spin_until(&ready_w[bx < 8 ? 0 : 1], 64);
            spin_until(&ready_x[by], 8);
        }
        __syncthreads();
        gemm_body<2>(xh, Wqkh, nullptr, QKh, DIM, DIM, 2048,
                     by * 256, bx * 128, DIM, cmul, sm, nullptr, nullptr, nullptr);
        __syncthreads();
        if (tid == 0) {
            __threadfence();
            atomicAdd(&ready_qk[by], 1);
        }
    } else if (bid < 1216) {
        // ---- V^T projection: bx 0..63 (token blocks), by 0..3 (D band)
        const int id2 = bid - 960;
        const int bx = id2 & 63, by = id2 >> 6;
        if (tid == 0) {
            spin_until(&ready_w[2], 64);
            spin_until(&ready_x[bx >> 1], 8);
        }
        __syncthreads();
        gemm_body<2>(Wvh, xh, nullptr, Vth, DIM, DIM, NTOK,
                     by * 256, bx * 128, DIM, 1.0f, sm, nullptr, nullptr, nullptr);
        __syncthreads();
        if (tid == 0) {
            __threadfence();
            atomicAdd(&ready_v[by * 4 + (bx >> 4)], 1);
        }
    } else if (bid < 1504) {
        // ---- scores block ----
        const int sid = bid - 1216;
        const int z = sid & 3;
        const int t = 71 - (sid >> 2);      // heavy bands first
        int i = 0;
        while ((i + 1) * (i + 2) <= t) ++i;
        const int j = t - i * (i + 1);

        if (tid == 0) {
            spin_until(&ready_qk[z * 8 + i], 16);          // Q band
            spin_until(&ready_qk[z * 8 + (j >> 1)], 16);   // K band
        }
        __syncthreads();

        const __half* A = QKh + (long)z * SEQ * 2048;
        const __half* B = QKh + 1024 + (long)z * SEQ * 2048;
        __half* Cc = Eh + (long)z * SEQ * SEQ;
        gemm_body<3>(A, B, nullptr, Cc, 2048, 2048, SEQ,
                     i * 256, j * 128, DIM, 1.0f, sm, rsum_sh,
                     rowsum + (long)z * SEQ, nullptr);

        __syncthreads();
        if (tid == 0) {
            __threadfence();
            atomicAdd(&ready_band[z * 8 + i], 1);
        }
    } else {
        // ---- PV block ----
        const int p = bid - 1504;
        const int z = p & 3;
        const int pp = p >> 2;              // 0..63
        const int by = 7 - (pp >> 3);       // heavy bands first
        const int bx = pp & 7;
        const int brow0 = by * 256;

        if (tid == 0) {
            spin_until(&ready_band[z * 8 + by], 2 * by + 2);   // scores band
            spin_until(&ready_v[(bx >> 1) * 4 + z], 16);       // V proj band
        }
        __syncthreads();

        const __half* A = Eh + (long)z * SEQ * SEQ;
        const __half* B = Vth + (long)z * SEQ;
        float* Cc = out + (long)z * SEQ * DIM;
        gemm_body<4>(A, B, Cc, nullptr, SEQ, NTOK, DIM,
                     brow0, bx * 128, brow0 + 256, 1.0f, sm,
                     nullptr, nullptr, rowsum + (long)z * SEQ);
    }
}

// ---------------------------------------------------------------------------
// Host launcher
// ---------------------------------------------------------------------------
extern "C" void kernel_launch(void* const* d_in, const int* in_sizes, int n_in,
                              void* d_out, int out_size)
{
    (void)in_sizes; (void)n_in; (void)out_size;
    const float* x  = (const float*)d_in[0];
    const float* Qw = (const float*)d_in[1];
    const float* Kw = (const float*)d_in[2];
    const float* Vw = (const float*)d_in[3];
    float* out = (float*)d_out;

    __half *xh, *Wqkh, *Wvh, *QKh, *Vth, *Eh;
    float* rowsum;
    int* ready;
    cudaGetSymbolAddress((void**)&xh,     g_xh);
    cudaGetSymbolAddress((void**)&Wqkh,   g_Wqkh);
    cudaGetSymbolAddress((void**)&Wvh,    g_Wvh);
    cudaGetSymbolAddress((void**)&QKh,    g_QKh);
    cudaGetSymbolAddress((void**)&Vth,    g_Vth);
    cudaGetSymbolAddress((void**)&Eh,     g_Eh);
    cudaGetSymbolAddress((void**)&rowsum, g_rowsum);
    cudaGetSymbolAddress((void**)&ready,  g_ready);

    cudaFuncSetAttribute(mega_k, cudaFuncAttributeMaxDynamicSharedMemorySize, SMEM_G);

    // Reset pipeline state (graph-capturable async memsets).
    cudaMemsetAsync(ready, 0, 116 * sizeof(int));
    cudaMemsetAsync(rowsum, 0, BATCH * SEQ * sizeof(float));

    // Entire computation: one counter-pipelined grid.
    mega_k<<<1760, 512, SMEM_G>>>(x, Qw, Kw, Vw, xh, Wqkh, Wvh,
                                  QKh, Vth, Eh, rowsum, out, ready);
}

// round 17
// speedup vs baseline: 1.0269x; 1.0039x over previous
#include <cuda_runtime.h>
#include <cuda_fp16.h>
#include <math.h>
#include <stdint.h>

// Problem shape (fixed by reference): B=4, S=2048, D=1024
#define BATCH 4
#define SEQ   2048
#define DIM   1024
#define NTOK  (BATCH * SEQ)   // 8192

// ---------------------------------------------------------------------------
// Scratch (static device globals)
// ---------------------------------------------------------------------------
__device__ __half g_xh[NTOK * DIM];
__device__ __half g_Wqkh[2048 * DIM];                        // [Qw^T; Kw^T] hi
__device__ __half g_Wvh[DIM * DIM];                          // Vw^T hi
__device__ __half g_QKh[NTOK * 2048];                        // Q(pre-scaled) | K
__device__ __half g_Vth[DIM * NTOK];                         // V^T [D, NTOK]
__device__ __half g_Eh[BATCH * SEQ * SEQ];                   // exp(logits), masked
__device__ float  g_rowsum[BATCH * SEQ];                     // softmax denominators
// counters: [0,32) qk row-band (16 each), [32,48) v (D-band x batch, 16 each),
//           [48,80) scores band (2i+2 each)
__device__ int    g_ready[80];

// ---------------------------------------------------------------------------
// Helpers
// ---------------------------------------------------------------------------
__device__ __forceinline__ uint32_t smem_u32(const void* p) {
    uint32_t a;
    asm("{ .reg .u64 t; cvta.to.shared.u64 t, %1; cvt.u32.u64 %0, t; }" : "=r"(a) : "l"(p));
    return a;
}

__device__ __forceinline__ void spin_until(const int* cp, int need) {
    int v;
    do {
        asm volatile("ld.acquire.gpu.u32 %0, [%1];" : "=r"(v) : "l"(cp) : "memory");
        if (v < need) __nanosleep(200);
    } while (v < need);
}

#define CP16(dst, src) \
    asm volatile("cp.async.cg.shared.global [%0], [%1], 16;" :: "r"(dst), "l"(src))

#define LDSM4(r, addr) \
    asm volatile("ldmatrix.sync.aligned.m8n8.x4.shared.b16 {%0,%1,%2,%3}, [%4];" \
        : "=r"((r)[0]), "=r"((r)[1]), "=r"((r)[2]), "=r"((r)[3]) : "r"(addr))

// fp32-accumulate MMA
#define MMA4(c, a, b0, b1) \
    asm volatile("mma.sync.aligned.m16n8k16.row.col.f32.f16.f16.f32 " \
        "{%0,%1,%2,%3}, {%4,%5,%6,%7}, {%8,%9}, {%0,%1,%2,%3};" \
        : "+f"((c)[0]), "+f"((c)[1]), "+f"((c)[2]), "+f"((c)[3]) \
        : "r"((a)[0]), "r"((a)[1]), "r"((a)[2]), "r"((a)[3]), "r"(b0), "r"(b1))

// ---------------------------------------------------------------------------
// Unified GEMM body: CTA tile 256x128, BK=64, 512 threads = 16 warps (4x4),
// warp tile 64x32, 3-stage cp.async pipeline, 144B pitch (conflict-free LDSM).
// EPI: 2 -> fp16 Ch, scaled by cmul
//      3 -> fp16 exp(acc) with causal mask; row sums -> rsum_sh -> rs_out
//      4 -> fp32 C divided by rs_in[row]
// ---------------------------------------------------------------------------
#define PITCH    144
#define TILE_A64 (256 * PITCH)     // 36864
#define TILE_B64 (128 * PITCH)     // 18432
#define STAGE_G  (TILE_A64 + TILE_B64)
#define SMEM_G   (3 * STAGE_G)     // 165888

template <int EPI>
__device__ __forceinline__ void gemm_body(
    const __half* __restrict__ Ah, const __half* __restrict__ Bh,
    float* __restrict__ C, __half* __restrict__ Ch,
    int lda, int ldb, int ldc, int brow0, int bcol0, int kend, float cmul,
    char* sm, float* rsum_sh, float* rs_out, const float* rs_in)
{
    const uint32_t smb = smem_u32(sm);

    const int tid = threadIdx.x;
    const int lane = tid & 31;
    const int wid = tid >> 5;     // 0..15
    const int wr = wid >> 2;      // 0..3 -> rows wr*64
    const int wc = wid & 3;       // 0..3 -> cols wc*32

    const int nsteps = kend >> 6;          // BK = 64

    const int lrow = tid >> 3;    // 0..63
    const int lcol = tid & 7;     // 0..7 (16B chunks over 128B row)
    const uint32_t soR = (uint32_t)(lrow * PITCH + lcol * 16);

    auto load_stage = [&](int slot, int k0) {
        uint32_t st = smb + slot * STAGE_G;
        long gk = k0 + lcol * 8;
#pragma unroll
        for (int h = 0; h < 4; h++)
            CP16(st + soR + h * (64 * PITCH),
                 Ah + (long)(brow0 + lrow + h * 64) * lda + gk);
#pragma unroll
        for (int h = 0; h < 2; h++)
            CP16(st + TILE_A64 + soR + h * (64 * PITCH),
                 Bh + (long)(bcol0 + lrow + h * 64) * ldb + gk);
        asm volatile("cp.async.commit_group;");
    };

    float acc[4][4][4];
#pragma unroll
    for (int mt = 0; mt < 4; mt++)
#pragma unroll
        for (int nt = 0; nt < 4; nt++)
#pragma unroll
            for (int v = 0; v < 4; v++) acc[mt][nt][v] = 0.f;

    const int arow = lane & 15;
    const int asel = lane >> 4;
    const int browi = (lane & 7) + ((lane >> 4) << 3);
    const int bsel = (lane >> 3) & 1;

#pragma unroll
    for (int k = 0; k < 2; k++) {
        if (k < nsteps) load_stage(k, k * 64);
        else asm volatile("cp.async.commit_group;");
    }

    for (int s = 0; s < nsteps; s++) {
        asm volatile("cp.async.wait_group 1;");
        __syncthreads();

        const uint32_t st = smb + (s % 3) * STAGE_G;
#pragma unroll
        for (int kk = 0; kk < 4; kk++) {
            uint32_t aH[4][4];
#pragma unroll
            for (int mt = 0; mt < 4; mt++) {
                uint32_t off = (uint32_t)((wr * 64 + mt * 16 + arow) * PITCH + kk * 32 + asel * 16);
                LDSM4(aH[mt], st + off);
            }
            uint32_t bH[2][4];
#pragma unroll
            for (int np = 0; np < 2; np++) {
                uint32_t off = (uint32_t)((wc * 32 + np * 16 + browi) * PITCH + kk * 32 + bsel * 16);
                LDSM4(bH[np], st + TILE_A64 + off);
            }
#pragma unroll
            for (int mt = 0; mt < 4; mt++)
#pragma unroll
                for (int nt = 0; nt < 4; nt++) {
                    const int np = nt >> 1, hv = (nt & 1) * 2;
                    MMA4(acc[mt][nt], aH[mt], bH[np][hv], bH[np][hv + 1]);
                }
        }

        if (s + 2 < nsteps) load_stage((s + 2) % 3, (s + 2) * 64);
        else asm volatile("cp.async.commit_group;");
    }

    // --- epilogue ---
    if (EPI == 3) {
        __syncthreads();
        if (tid < 256) rsum_sh[tid] = 0.f;
        __syncthreads();
    }

    const int erow = lane >> 2;
    const int ecol = (lane & 3) * 2;
#pragma unroll
    for (int mt = 0; mt < 4; mt++) {
        const int row = brow0 + wr * 64 + mt * 16 + erow;
        float rp0 = 0.f, rp1 = 0.f;         // EPI==3 row partials
        float i0 = 1.f, i1 = 1.f;
        if (EPI == 4) {
            i0 = __frcp_rn(rs_in[row]);
            i1 = __frcp_rn(rs_in[row + 8]);
        }
#pragma unroll
        for (int nt = 0; nt < 4; nt++) {
            const int col = bcol0 + wc * 32 + nt * 8 + ecol;
            float c0 = acc[mt][nt][0], c1 = acc[mt][nt][1];
            float c2 = acc[mt][nt][2], c3 = acc[mt][nt][3];
            if (EPI == 4) {
                c0 *= i0; c1 *= i0; c2 *= i1; c3 *= i1;
                *(float2*)(C + (long)row * ldc + col)       = make_float2(c0, c1);
                *(float2*)(C + (long)(row + 8) * ldc + col) = make_float2(c2, c3);
            } else if (EPI == 2) {
                c0 *= cmul; c1 *= cmul; c2 *= cmul; c3 *= cmul;
                *(__half2*)(Ch + (long)row * ldc + col) =
                    __halves2half2(__float2half_rn(c0), __float2half_rn(c1));
                *(__half2*)(Ch + (long)(row + 8) * ldc + col) =
                    __halves2half2(__float2half_rn(c2), __float2half_rn(c3));
            } else { // EPI == 3: exp + causal mask + row sums
                float e0 = (col     <= row)     ? __expf(c0) : 0.f;
                float e1 = (col + 1 <= row)     ? __expf(c1) : 0.f;
                float e2 = (col     <= row + 8) ? __expf(c2) : 0.f;
                float e3 = (col + 1 <= row + 8) ? __expf(c3) : 0.f;
                *(__half2*)(Ch + (long)row * ldc + col) =
                    __halves2half2(__float2half_rn(e0), __float2half_rn(e1));
                *(__half2*)(Ch + (long)(row + 8) * ldc + col) =
                    __halves2half2(__float2half_rn(e2), __float2half_rn(e3));
                rp0 += e0 + e1;
                rp1 += e2 + e3;
            }
        }
        if (EPI == 3) {
            rp0 += __shfl_xor_sync(0xFFFFFFFFu, rp0, 1);
            rp0 += __shfl_xor_sync(0xFFFFFFFFu, rp0, 2);
            rp1 += __shfl_xor_sync(0xFFFFFFFFu, rp1, 1);
            rp1 += __shfl_xor_sync(0xFFFFFFFFu, rp1, 2);
            if ((lane & 3) == 0) {
                const int rl = wr * 64 + mt * 16 + erow;
                atomicAdd(&rsum_sh[rl],     rp0);
                atomicAdd(&rsum_sh[rl + 8], rp1);
            }
        }
    }
    if (EPI == 3) {
        __syncthreads();
        if (tid < 256) atomicAdd(&rs_out[brow0 + tid], rsum_sh[tid]);
    }
}

// ---------------------------------------------------------------------------
// Mega kernel (round-14 structure): one grid, counter-pipelined stages.
//   ids [0,512):    QK projection (batch-major bands; Q half pre-scaled).
//   ids [512,768):  V^T projection.
//   ids [768,1056): scores+exp+rowsum, gated on ready_qk; heavy bands first.
//   ids [1056,1312): PV, gated on scores band + ready_v counters.
// ---------------------------------------------------------------------------
__global__ void __launch_bounds__(512, 1)
mega_k(const __half* __restrict__ xh, const __half* __restrict__ Wqkh,
       const __half* __restrict__ Wvh, __half* __restrict__ QKh,
       __half* __restrict__ Vth, __half* __restrict__ Eh,
       float* __restrict__ rowsum, float* __restrict__ out,
       int* __restrict__ ready)
{
    extern __shared__ char sm[];
    __shared__ float rsum_sh[256];
    const int bid = blockIdx.x;
    const int tid = threadIdx.x;

    int* ready_qk   = ready;         // [0,32)
    int* ready_v    = ready + 32;    // [32,48)
    int* ready_band = ready + 48;    // [48,80)

    if (bid < 512) {
        // ---- QK projection: bx 0..15 (cols), by 0..31 (row band, batch-major)
        const int bx = bid & 15, by = bid >> 4;
        const float cmul = (bx < 8) ? 0.03125f : 1.0f;   // scale Q columns only
        gemm_body<2>(xh, Wqkh, nullptr, QKh, DIM, DIM, 2048,
                     by * 256, bx * 128, DIM, cmul, sm, nullptr, nullptr, nullptr);
        __syncthreads();
        if (tid == 0) {
            __threadfence();
            atomicAdd(&ready_qk[by], 1);
        }
    } else if (bid < 768) {
        // ---- V^T projection: bx 0..63 (token blocks), by 0..3 (D band)
        const int id2 = bid - 512;
        const int bx = id2 & 63, by = id2 >> 6;
        gemm_body<2>(Wvh, xh, nullptr, Vth, DIM, DIM, NTOK,
                     by * 256, bx * 128, DIM, 1.0f, sm, nullptr, nullptr, nullptr);
        __syncthreads();
        if (tid == 0) {
            __threadfence();
            atomicAdd(&ready_v[by * 4 + (bx >> 4)], 1);
        }
    } else if (bid < 1056) {
        // ---- scores block ----
        const int sid = bid - 768;
        const int z = sid & 3;
        const int t = 71 - (sid >> 2);      // heavy bands first
        int i = 0;
        while ((i + 1) * (i + 2) <= t) ++i;
        const int j = t - i * (i + 1);

        if (tid == 0) {
            spin_until(&ready_qk[z * 8 + i], 16);          // Q band
            spin_until(&ready_qk[z * 8 + (j >> 1)], 16);   // K band
        }
        __syncthreads();

        const __half* A = QKh + (long)z * SEQ * 2048;
        const __half* B = QKh + 1024 + (long)z * SEQ * 2048;
        __half* Cc = Eh + (long)z * SEQ * SEQ;
        gemm_body<3>(A, B, nullptr, Cc, 2048, 2048, SEQ,
                     i * 256, j * 128, DIM, 1.0f, sm, rsum_sh,
                     rowsum + (long)z * SEQ, nullptr);

        __syncthreads();
        if (tid == 0) {
            __threadfence();
            atomicAdd(&ready_band[z * 8 + i], 1);
        }
    } else {
        // ---- PV block ----
        const int p = bid - 1056;
        const int z = p & 3;
        const int pp = p >> 2;              // 0..63
        const int by = 7 - (pp >> 3);       // heavy bands first
        const int bx = pp & 7;
        const int brow0 = by * 256;

        if (tid == 0) {
            spin_until(&ready_band[z * 8 + by], 2 * by + 2);   // scores band
            spin_until(&ready_v[(bx >> 1) * 4 + z], 16);       // V proj band
        }
        __syncthreads();

        const __half* A = Eh + (long)z * SEQ * SEQ;
        const __half* B = Vth + (long)z * SEQ;
        float* Cc = out + (long)z * SEQ * DIM;
        gemm_body<4>(A, B, Cc, nullptr, SEQ, NTOK, DIM,
                     brow0, bx * 128, brow0 + 256, 1.0f, sm,
                     nullptr, nullptr, rowsum + (long)z * SEQ);
    }
}

// ---------------------------------------------------------------------------
// Fused prep: z<3 -> weight transpose (half2-vectorized stores);
//             z==3 -> x fp32->fp16 convert + rowsum/ready zeroing (block 0).
// grid (32, 32, 4), block (32, 8).
// ---------------------------------------------------------------------------
__global__ void __launch_bounds__(256)
prep_k(const float* __restrict__ x, const float* __restrict__ Qw,
       const float* __restrict__ Kw, const float* __restrict__ Vw,
       __half* __restrict__ xh, __half* __restrict__ Wqkh,
       __half* __restrict__ Wvh, float* __restrict__ rowsum,
       int* __restrict__ ready)
{
    const int z = blockIdx.z;
    if (z < 3) {
        __shared__ float tile[32][33];
        const float* src = (z == 0) ? Qw : (z == 1) ? Kw : Vw;
        __half* dst = (z == 0) ? Wqkh : (z == 1) ? (Wqkh + DIM * DIM) : Wvh;
        const int c0 = blockIdx.x * 32, r0 = blockIdx.y * 32;
#pragma unroll
        for (int dy = threadIdx.y; dy < 32; dy += 8)
            tile[dy][threadIdx.x] = src[(long)(r0 + dy) * DIM + c0 + threadIdx.x];
        __syncthreads();
        // vectorized writes: thread (txh, dyq) covers output column c0+dy,
        // rows r0 + 2*txh .. +1 as one __half2 store.
        const int txh = threadIdx.x & 15;               // 0..15 -> row pair
        const int dy0 = threadIdx.y + ((threadIdx.x >> 4) << 3);  // 0..15
#pragma unroll
        for (int dy = dy0; dy < 32; dy += 16) {
            __half2 v = __halves2half2(__float2half_rn(tile[2 * txh][dy]),
                                       __float2half_rn(tile[2 * txh + 1][dy]));
            *(__half2*)(dst + (long)(c0 + dy) * DIM + r0 + 2 * txh) = v;
        }
    } else {
        const long n4 = (long)NTOK * DIM / 4;
        const int bid = blockIdx.y * 32 + blockIdx.x;
        const int tid = threadIdx.y * 32 + threadIdx.x;
        if (bid == 0) {
            for (int i = tid; i < BATCH * SEQ; i += 256) rowsum[i] = 0.f;
            if (tid < 80) ready[tid] = 0;
        }
        long idx = (long)bid * 256 + tid;
        const long stride = 1024L * 256;
        for (; idx < n4; idx += stride) {
            float4 v = ((const float4*)x)[idx];
            __half h[4] = {__float2half_rn(v.x), __float2half_rn(v.y),
                           __float2half_rn(v.z), __float2half_rn(v.w)};
            ((uint2*)xh)[idx] = *(uint2*)h;
        }
    }
}

// ---------------------------------------------------------------------------
// Host launcher
// ---------------------------------------------------------------------------
extern "C" void kernel_launch(void* const* d_in, const int* in_sizes, int n_in,
                              void* d_out, int out_size)
{
    (void)in_sizes; (void)n_in; (void)out_size;
    const float* x  = (const float*)d_in[0];
    const float* Qw = (const float*)d_in[1];
    const float* Kw = (const float*)d_in[2];
    const float* Vw = (const float*)d_in[3];
    float* out = (float*)d_out;

    __half *xh, *Wqkh, *Wvh, *QKh, *Vth, *Eh;
    float* rowsum;
    int* ready;
    cudaGetSymbolAddress((void**)&xh,     g_xh);
    cudaGetSymbolAddress((void**)&Wqkh,   g_Wqkh);
    cudaGetSymbolAddress((void**)&Wvh,    g_Wvh);
    cudaGetSymbolAddress((void**)&QKh,    g_QKh);
    cudaGetSymbolAddress((void**)&Vth,    g_Vth);
    cudaGetSymbolAddress((void**)&Eh,     g_Eh);
    cudaGetSymbolAddress((void**)&rowsum, g_rowsum);
    cudaGetSymbolAddress((void**)&ready,  g_ready);

    cudaFuncSetAttribute(mega_k, cudaFuncAttributeMaxDynamicSharedMemorySize, SMEM_G);

    // --- Prep: convert x + transpose 3 weights + zero counters ---
    {
        dim3 tg(32, 32, 4);
        dim3 tb(32, 8);
        prep_k<<<tg, tb>>>(x, Qw, Kw, Vw, xh, Wqkh, Wvh, rowsum, ready);
    }

    // --- Everything else: one counter-pipelined grid ---
    mega_k<<<1312, 512, SMEM_G>>>(xh, Wqkh, Wvh, QKh, Vth, Eh, rowsum, out, ready);
}